// round 2
// baseline (speedup 1.0000x reference)
#include <cuda_runtime.h>
#include <cstdint>
#include <cstddef>

// Problem constants
#define BATCH   2
#define SEQ     2048
#define DMODEL  1024
#define NHEADS  16
#define NPHYS   8
#define DHEAD   64
#define ROWS    (BATCH * SEQ)          // 4096
#define QKVCOLS (3 * DMODEL)           // 3072

// Scratch (device globals: allocation-free contract)
__device__ float g_qkv[(size_t)ROWS * QKVCOLS];   // [4096, 3072]  q|k|v packed
__device__ float g_att[(size_t)ROWS * DMODEL];    // [4096, 1024]  attention output, head-major cols

// ---------------------------------------------------------------------------
// SGEMM: C[M,N] = A[M,K] @ B[K,N], all row-major fp32.
// 128x128 tile, BK=8, 256 threads, 8x8 per thread.
// 2-stage smem double buffer with register-staged prefetch.
// ---------------------------------------------------------------------------
__global__ __launch_bounds__(256) void sgemm128(
    const float* __restrict__ A, const float* __restrict__ B, float* __restrict__ C,
    int M, int N, int K)
{
    __shared__ float As[2][8][128];
    __shared__ float Bs[2][8][128];

    const int tid = threadIdx.x;
    const int tx = tid & 15;       // 0..15  -> col group
    const int ty = tid >> 4;       // 0..15  -> row group
    const int row0 = blockIdx.y * 128;
    const int col0 = blockIdx.x * 128;

    // A-tile load mapping: one float4 per thread (128 rows x 2 float4)
    const int arow = tid >> 1;
    const int acol = (tid & 1) * 4;
    // B-tile load mapping: one float4 per thread (8 rows x 32 float4)
    const int brow = tid >> 5;
    const int bcol = (tid & 31) * 4;

    const float* Aptr = A + (size_t)(row0 + arow) * K + acol;
    const float* Bptr = B + (size_t)brow * N + col0 + bcol;

    float acc[8][8];
#pragma unroll
    for (int i = 0; i < 8; i++)
#pragma unroll
        for (int j = 0; j < 8; j++) acc[i][j] = 0.f;

    // prologue: load tile 0 into buffer 0
    {
        float4 a4 = *(const float4*)(Aptr);
        float4 b4 = *(const float4*)(Bptr);
        As[0][acol + 0][arow] = a4.x;
        As[0][acol + 1][arow] = a4.y;
        As[0][acol + 2][arow] = a4.z;
        As[0][acol + 3][arow] = a4.w;
        *(float4*)&Bs[0][brow][bcol] = b4;
    }
    __syncthreads();

    int buf = 0;
    for (int k0 = 0; k0 < K; k0 += 8) {
        // prefetch next tile into registers (overlaps with math below)
        float4 a4n, b4n;
        const bool have_next = (k0 + 8) < K;
        if (have_next) {
            a4n = *(const float4*)(Aptr + k0 + 8);
            b4n = *(const float4*)(Bptr + (size_t)(k0 + 8) * N);
        }

#pragma unroll
        for (int kk = 0; kk < 8; kk++) {
            float a[8], b[8];
            *(float4*)(a)     = *(const float4*)&As[buf][kk][ty * 8];
            *(float4*)(a + 4) = *(const float4*)&As[buf][kk][ty * 8 + 4];
            *(float4*)(b)     = *(const float4*)&Bs[buf][kk][tx * 8];
            *(float4*)(b + 4) = *(const float4*)&Bs[buf][kk][tx * 8 + 4];
#pragma unroll
            for (int i = 0; i < 8; i++)
#pragma unroll
                for (int j = 0; j < 8; j++) acc[i][j] += a[i] * b[j];
        }

        if (have_next) {
            int nb = buf ^ 1;
            As[nb][acol + 0][arow] = a4n.x;
            As[nb][acol + 1][arow] = a4n.y;
            As[nb][acol + 2][arow] = a4n.z;
            As[nb][acol + 3][arow] = a4n.w;
            *(float4*)&Bs[nb][brow][bcol] = b4n;
            __syncthreads();
            buf = nb;
        }
    }

#pragma unroll
    for (int i = 0; i < 8; i++) {
        float* Crow = C + (size_t)(row0 + ty * 8 + i) * N + col0 + tx * 8;
        *(float4*)(Crow)     = make_float4(acc[i][0], acc[i][1], acc[i][2], acc[i][3]);
        *(float4*)(Crow + 4) = make_float4(acc[i][4], acc[i][5], acc[i][6], acc[i][7]);
    }
}

// ---------------------------------------------------------------------------
// Flash attention: one CTA per (b, h, 64-query tile). 256 threads as 16x16.
// Each thread owns a 4x4 fragment of the 64x64 S/P tile and a 4x4 fragment
// of the 64(q) x 64(dh) O accumulator. Online softmax; m/l kept redundantly
// in registers per thread-row (reduced over tx via half-warp shuffles).
// Dynamic smem (64 KB): Qt[64][64] ([d][i], pre-scaled), Kt[64][64] ([d][j]),
// V[64][64] ([j][d]), P[64][64] ([i][j]).
// ---------------------------------------------------------------------------
__global__ __launch_bounds__(256) void flash_attn(
    const float* __restrict__ qkv,      // [4096, 3072]
    const float* __restrict__ attn_bias,// [B, 1, N, N]
    const float* __restrict__ beta,     // [8]
    float* __restrict__ out)            // [4096, 1024], col h*64+d
{
    extern __shared__ float smem[];
    float* Qt = smem;            // 4096 floats
    float* Kt = smem + 4096;
    float* Vsh = smem + 8192;
    float* Psh = smem + 12288;

    const int qt = blockIdx.x;   // 0..31
    const int h  = blockIdx.y;   // 0..15
    const int b  = blockIdx.z;   // 0..1

    const int tid = threadIdx.x;
    const int tx = tid & 15;
    const int ty = tid >> 4;
    const int i0 = ty * 4;       // query-row group within tile
    const int c0 = tx * 4;       // key-col group (for S) / dh-col group (for O)

    const float scale = 0.125f;  // 1/sqrt(64)
    const float bbeta = (h < NPHYS) ? beta[h] : 0.f;

    // Load Q tile [64 x 64] -> Qt[d][i], pre-scaled
#pragma unroll
    for (int it = 0; it < 4; it++) {
        int idx = tid + it * 256;       // 0..1023 float4 slots
        int i = idx >> 4;               // row in tile
        int d4 = (idx & 15) * 4;        // dh offset
        const float* src = qkv + ((size_t)(b * SEQ + qt * 64 + i)) * QKVCOLS + h * DHEAD + d4;
        float4 v = *(const float4*)src;
        Qt[(d4 + 0) * 64 + i] = v.x * scale;
        Qt[(d4 + 1) * 64 + i] = v.y * scale;
        Qt[(d4 + 2) * 64 + i] = v.z * scale;
        Qt[(d4 + 3) * 64 + i] = v.w * scale;
    }

    float m_r[4], l_r[4], O[4][4];
#pragma unroll
    for (int r = 0; r < 4; r++) {
        m_r[r] = -1e30f; l_r[r] = 0.f;
#pragma unroll
        for (int c = 0; c < 4; c++) O[r][c] = 0.f;
    }

    const float* bias_base = attn_bias + (size_t)b * SEQ * SEQ + (size_t)(qt * 64) * SEQ;

    for (int jt = 0; jt < 32; jt++) {
        __syncthreads();  // prior-iter AV reads of V / P done before overwrite

        // Load K -> Kt[d][j], V -> Vsh[j][d]
#pragma unroll
        for (int it = 0; it < 4; it++) {
            int idx = tid + it * 256;
            int j = idx >> 4;
            int d4 = (idx & 15) * 4;
            size_t rowoff = ((size_t)(b * SEQ + jt * 64 + j)) * QKVCOLS + h * DHEAD;
            float4 kv = *(const float4*)(qkv + rowoff + DMODEL + d4);
            Kt[(d4 + 0) * 64 + j] = kv.x;
            Kt[(d4 + 1) * 64 + j] = kv.y;
            Kt[(d4 + 2) * 64 + j] = kv.z;
            Kt[(d4 + 3) * 64 + j] = kv.w;
            float4 vv = *(const float4*)(qkv + rowoff + 2 * DMODEL + d4);
            *(float4*)&Vsh[j * 64 + d4] = vv;
        }
        __syncthreads();

        // S = (Q*scale) K^T, 4x4 per thread
        float S[4][4];
#pragma unroll
        for (int r = 0; r < 4; r++)
#pragma unroll
            for (int c = 0; c < 4; c++) S[r][c] = 0.f;

#pragma unroll 16
        for (int d = 0; d < 64; d++) {
            float4 q4 = *(const float4*)&Qt[d * 64 + i0];
            float4 k4 = *(const float4*)&Kt[d * 64 + c0];
            float q[4] = {q4.x, q4.y, q4.z, q4.w};
            float k[4] = {k4.x, k4.y, k4.z, k4.w};
#pragma unroll
            for (int r = 0; r < 4; r++)
#pragma unroll
                for (int c = 0; c < 4; c++) S[r][c] += q[r] * k[c];
        }

        // additive bias on physical heads
        if (h < NPHYS) {
#pragma unroll
            for (int r = 0; r < 4; r++) {
                float4 bv = *(const float4*)(bias_base + (size_t)(i0 + r) * SEQ + jt * 64 + c0);
                S[r][0] += bbeta * bv.x;
                S[r][1] += bbeta * bv.y;
                S[r][2] += bbeta * bv.z;
                S[r][3] += bbeta * bv.w;
            }
        }

        // online softmax per row (reduce over the 16 tx lanes in the half-warp)
#pragma unroll
        for (int r = 0; r < 4; r++) {
            float mx = fmaxf(fmaxf(S[r][0], S[r][1]), fmaxf(S[r][2], S[r][3]));
#pragma unroll
            for (int off = 1; off < 16; off <<= 1)
                mx = fmaxf(mx, __shfl_xor_sync(0xffffffffu, mx, off));
            float mnew = fmaxf(m_r[r], mx);
            float corr = __expf(m_r[r] - mnew);
            float p0 = __expf(S[r][0] - mnew);
            float p1 = __expf(S[r][1] - mnew);
            float p2 = __expf(S[r][2] - mnew);
            float p3 = __expf(S[r][3] - mnew);
            float rs = (p0 + p1) + (p2 + p3);
#pragma unroll
            for (int off = 1; off < 16; off <<= 1)
                rs += __shfl_xor_sync(0xffffffffu, rs, off);
            l_r[r] = l_r[r] * corr + rs;
            m_r[r] = mnew;
#pragma unroll
            for (int c = 0; c < 4; c++) O[r][c] *= corr;
            *(float4*)&Psh[(i0 + r) * 64 + c0] = make_float4(p0, p1, p2, p3);
        }
        __syncthreads();  // P fully written, V loaded

        // O += P @ V  (thread owns rows i0..i0+3, dh cols c0..c0+3)
#pragma unroll 8
        for (int j = 0; j < 64; j++) {
            float4 v4 = *(const float4*)&Vsh[j * 64 + c0];
            float p[4];
#pragma unroll
            for (int r = 0; r < 4; r++) p[r] = Psh[(i0 + r) * 64 + j];
#pragma unroll
            for (int r = 0; r < 4; r++) {
                O[r][0] += p[r] * v4.x;
                O[r][1] += p[r] * v4.y;
                O[r][2] += p[r] * v4.z;
                O[r][3] += p[r] * v4.w;
            }
        }
    }

    // epilogue: normalize and write [row, h*64 + d]
#pragma unroll
    for (int r = 0; r < 4; r++) {
        float inv = 1.f / l_r[r];
        float4 o4 = make_float4(O[r][0] * inv, O[r][1] * inv, O[r][2] * inv, O[r][3] * inv);
        *(float4*)(out + ((size_t)(b * SEQ + qt * 64 + i0 + r)) * DMODEL + h * DHEAD + c0) = o4;
    }
}

// ---------------------------------------------------------------------------
extern "C" void kernel_launch(void* const* d_in, const int* in_sizes, int n_in,
                              void* d_out, int out_size)
{
    const float* x         = (const float*)d_in[0];  // [2,2048,1024]
    const float* attn_bias = (const float*)d_in[1];  // [2,1,2048,2048]
    const float* Wqkv      = (const float*)d_in[2];  // [1024,3072]
    const float* Wproj     = (const float*)d_in[3];  // [1024,1024]
    const float* beta      = (const float*)d_in[4];  // [8]
    float* out = (float*)d_out;                      // [2,2048,1024]

    float* qkv_s = nullptr;
    float* att_s = nullptr;
    cudaGetSymbolAddress((void**)&qkv_s, g_qkv);
    cudaGetSymbolAddress((void**)&att_s, g_att);

    cudaFuncSetAttribute(flash_attn, cudaFuncAttributeMaxDynamicSharedMemorySize, 65536);

    // 1) qkv = x @ Wqkv     [4096,1024]x[1024,3072]
    sgemm128<<<dim3(QKVCOLS / 128, ROWS / 128), 256>>>(x, Wqkv, qkv_s, ROWS, QKVCOLS, DMODEL);

    // 2) attention (flash) -> g_att [4096, 1024] head-major columns
    flash_attn<<<dim3(SEQ / 64, NHEADS, BATCH), 256, 65536>>>(qkv_s, attn_bias, beta, att_s);

    // 3) out = att @ Wproj  [4096,1024]x[1024,1024]
    sgemm128<<<dim3(DMODEL / 128, ROWS / 128), 256>>>(att_s, Wproj, out, ROWS, DMODEL, DMODEL);
}

// round 4
// speedup vs baseline: 2.6098x; 2.6098x over previous
#include <cuda_runtime.h>
#include <cstdint>
#include <cstddef>

#define BATCH   2
#define SEQ     2048
#define DMODEL  1024
#define NHEADS  16
#define NPHYS   8
#define DHEAD   64
#define ROWS    (BATCH * SEQ)          // 4096
#define QKVCOLS (3 * DMODEL)           // 3072

// Scratch (device globals: allocation-free contract). All tf32-bit arrays as uint32.
__device__ uint32_t g_xc[(size_t)ROWS * DMODEL];       // x converted to tf32 bits
__device__ uint32_t g_wqkvc[(size_t)DMODEL * QKVCOLS]; // Wqkv tf32
__device__ uint32_t g_wprojc[(size_t)DMODEL * DMODEL]; // Wproj tf32
__device__ uint32_t g_qkv[(size_t)ROWS * QKVCOLS];     // qkv (tf32 bits)
__device__ uint32_t g_att[(size_t)ROWS * DMODEL];      // attention out (tf32 bits)

__device__ __forceinline__ uint32_t f2tf(float x) {
    uint32_t r; asm("cvt.rna.tf32.f32 %0, %1;" : "=r"(r) : "f"(x)); return r;
}

// m16n8k8 tf32 MMA, D = A*B + D (in place)
__device__ __forceinline__ void mma8(float* c, const uint32_t* a, const uint32_t* b) {
    asm volatile(
        "mma.sync.aligned.m16n8k8.row.col.f32.tf32.tf32.f32 "
        "{%0,%1,%2,%3},{%4,%5,%6,%7},{%8,%9},{%0,%1,%2,%3};"
        : "+f"(c[0]), "+f"(c[1]), "+f"(c[2]), "+f"(c[3])
        : "r"(a[0]), "r"(a[1]), "r"(a[2]), "r"(a[3]), "r"(b[0]), "r"(b[1]));
}

// ---------------------------------------------------------------------------
// Elementwise fp32 -> tf32-bits conversion (vectorized)
// ---------------------------------------------------------------------------
__global__ void cvt_tf32_kernel(const float4* __restrict__ in, uint4* __restrict__ out, int n4) {
    int i = blockIdx.x * blockDim.x + threadIdx.x;
    if (i < n4) {
        float4 v = in[i];
        out[i] = make_uint4(f2tf(v.x), f2tf(v.y), f2tf(v.z), f2tf(v.w));
    }
}

// ---------------------------------------------------------------------------
// tf32 tensor-core GEMM: C[M,N] = A[M,K] @ B[K,N], A/B are tf32 bits.
// CTA 128x128, BK=32, 256 threads, 8 warps in 4(m) x 2(n) grid, warp tile 32x64.
// Smem (dynamic 70656B): As[2][128][36] m-major pad4, Bs[2][32][132] k-major pad4.
// CVT_OUT: emit tf32 bits; else raw fp32 bits.
// ---------------------------------------------------------------------------
template<bool CVT_OUT>
__global__ __launch_bounds__(256) void gemm_tc(
    const uint32_t* __restrict__ A, const uint32_t* __restrict__ B, uint32_t* __restrict__ C,
    int M, int N, int K)
{
    extern __shared__ uint32_t ds[];
    const int tid = threadIdx.x, lane = tid & 31;
    const int g = lane >> 2, tg = lane & 3;
    const int w = tid >> 5, wm = w & 3, wn = w >> 2;
    const int row0 = blockIdx.y * 128, col0 = blockIdx.x * 128;

    const int ar = tid >> 3, ac = (tid & 7) * 4;   // A: 32 rows / iter, 4 iters
    const int br = tid >> 5, bc = (tid & 31) * 4;  // B: 8 rows / iter, 4 iters

    float acc[2][8][4];
#pragma unroll
    for (int m = 0; m < 2; m++)
#pragma unroll
        for (int n = 0; n < 8; n++)
#pragma unroll
            for (int c = 0; c < 4; c++) acc[m][n][c] = 0.f;

    uint4 pa[4], pb[4];
#pragma unroll
    for (int it = 0; it < 4; it++) {
        pa[it] = *(const uint4*)&A[(size_t)(row0 + ar + it * 32) * K + ac];
        pb[it] = *(const uint4*)&B[(size_t)(br + it * 8) * N + col0 + bc];
    }
    int buf = 0;
#pragma unroll
    for (int it = 0; it < 4; it++) {
        *(uint4*)&ds[buf * 4608 + (ar + it * 32) * 36 + ac] = pa[it];
        *(uint4*)&ds[9216 + buf * 4224 + (br + it * 8) * 132 + bc] = pb[it];
    }
    __syncthreads();

    for (int k0 = 0; k0 < K; k0 += 32) {
        const bool nxt = (k0 + 32) < K;
        if (nxt) {
#pragma unroll
            for (int it = 0; it < 4; it++) {
                pa[it] = *(const uint4*)&A[(size_t)(row0 + ar + it * 32) * K + k0 + 32 + ac];
                pb[it] = *(const uint4*)&B[(size_t)(k0 + 32 + br + it * 8) * N + col0 + bc];
            }
        }
        const uint32_t* Asb = ds + buf * 4608;
        const uint32_t* Bsb = ds + 9216 + buf * 4224;
#pragma unroll
        for (int kk = 0; kk < 32; kk += 8) {
            uint32_t a[2][4];
#pragma unroll
            for (int mt = 0; mt < 2; mt++) {
                const int r = wm * 32 + mt * 16 + g;
                a[mt][0] = Asb[r * 36 + kk + tg];
                a[mt][1] = Asb[(r + 8) * 36 + kk + tg];
                a[mt][2] = Asb[r * 36 + kk + tg + 4];
                a[mt][3] = Asb[(r + 8) * 36 + kk + tg + 4];
            }
#pragma unroll
            for (int nt = 0; nt < 8; nt++) {
                const int n = wn * 64 + nt * 8 + g;
                uint32_t bf[2];
                bf[0] = Bsb[(kk + tg) * 132 + n];
                bf[1] = Bsb[(kk + tg + 4) * 132 + n];
                mma8(acc[0][nt], a[0], bf);
                mma8(acc[1][nt], a[1], bf);
            }
        }
        if (nxt) {
            buf ^= 1;
#pragma unroll
            for (int it = 0; it < 4; it++) {
                *(uint4*)&ds[buf * 4608 + (ar + it * 32) * 36 + ac] = pa[it];
                *(uint4*)&ds[9216 + buf * 4224 + (br + it * 8) * 132 + bc] = pb[it];
            }
            __syncthreads();
        }
    }

#pragma unroll
    for (int mt = 0; mt < 2; mt++) {
        const int r0 = row0 + wm * 32 + mt * 16 + g;
#pragma unroll
        for (int nt = 0; nt < 8; nt++) {
            const int cc = col0 + wn * 64 + nt * 8 + 2 * tg;
            if (CVT_OUT) {
                *(uint2*)&C[(size_t)r0 * N + cc] =
                    make_uint2(f2tf(acc[mt][nt][0]), f2tf(acc[mt][nt][1]));
                *(uint2*)&C[(size_t)(r0 + 8) * N + cc] =
                    make_uint2(f2tf(acc[mt][nt][2]), f2tf(acc[mt][nt][3]));
            } else {
                *(uint2*)&C[(size_t)r0 * N + cc] =
                    make_uint2(__float_as_uint(acc[mt][nt][0]), __float_as_uint(acc[mt][nt][1]));
                *(uint2*)&C[(size_t)(r0 + 8) * N + cc] =
                    make_uint2(__float_as_uint(acc[mt][nt][2]), __float_as_uint(acc[mt][nt][3]));
            }
        }
    }
}

// ---------------------------------------------------------------------------
// Flash attention on tf32 MMAs. CTA = (b, h, 64-query tile), 256 thr, 8 warps
// in 4(m) x 2(n) grid; warp owns 16 rows x 32 cols of S and of O.
// Smem (88064B): Qs/Ks/Vs/Ps [64][68] tf32 bits, Bb [64][68] fp32 bias,
// rmax/rsum [2][64] cross-warp softmax scratch.
// ---------------------------------------------------------------------------
__global__ __launch_bounds__(256) void flash_attn_tc(
    const uint32_t* __restrict__ qkv, const float* __restrict__ bias,
    const float* __restrict__ beta, uint32_t* __restrict__ att)
{
    extern __shared__ uint32_t sm[];
    uint32_t* Qs = sm;              // [64][68]
    uint32_t* Ks = sm + 4352;
    uint32_t* Vs = sm + 2 * 4352;
    uint32_t* Ps = sm + 3 * 4352;
    float* Bb    = (float*)(sm + 4 * 4352);
    float* rmax  = (float*)(sm + 5 * 4352);  // [2][64]
    float* rsum  = rmax + 128;

    const int qt = blockIdx.x, h = blockIdx.y, b = blockIdx.z;
    const int tid = threadIdx.x, lane = tid & 31;
    const int g = lane >> 2, tg = lane & 3;
    const int w = tid >> 5, wm = w & 3, wn = w >> 2;
    const int r0 = wm * 16 + g, r1 = r0 + 8;
    const bool phys = (h < NPHYS);
    const float bb = phys ? beta[h] : 0.f;

    const size_t qbase = (size_t)(b * SEQ + qt * 64) * QKVCOLS + h * DHEAD;
#pragma unroll
    for (int it = 0; it < 4; it++) {
        int idx = tid + it * 256;
        int i = idx >> 4, d4 = (idx & 15) * 4;
        *(uint4*)&Qs[i * 68 + d4] = *(const uint4*)&qkv[qbase + (size_t)i * QKVCOLS + d4];
    }

    float O[4][4];
    float m0 = -1e30f, m1 = -1e30f, l0 = 0.f, l1 = 0.f;
#pragma unroll
    for (int nt = 0; nt < 4; nt++)
#pragma unroll
        for (int c = 0; c < 4; c++) O[nt][c] = 0.f;

    const float* bias_b = bias + (size_t)b * SEQ * SEQ + (size_t)(qt * 64) * SEQ;

    for (int jt = 0; jt < 32; jt++) {
        __syncthreads();  // prior PV reads of Vs/Ps done; Bb reads done
        const size_t kbase = (size_t)(b * SEQ + jt * 64) * QKVCOLS + h * DHEAD;
#pragma unroll
        for (int it = 0; it < 4; it++) {
            int idx = tid + it * 256;
            int j = idx >> 4, d4 = (idx & 15) * 4;
            *(uint4*)&Ks[j * 68 + d4] =
                *(const uint4*)&qkv[kbase + (size_t)j * QKVCOLS + DMODEL + d4];
            *(uint4*)&Vs[j * 68 + d4] =
                *(const uint4*)&qkv[kbase + (size_t)j * QKVCOLS + 2 * DMODEL + d4];
        }
        if (phys) {
#pragma unroll
            for (int it = 0; it < 4; it++) {
                int idx = tid + it * 256;
                int i = idx >> 4, c4 = (idx & 15) * 4;
                *(float4*)&Bb[i * 68 + c4] =
                    *(const float4*)&bias_b[(size_t)i * SEQ + jt * 64 + c4];
            }
        }
        __syncthreads();

        // ---- S = Q K^T ----
        float S[4][4];
#pragma unroll
        for (int nt = 0; nt < 4; nt++)
#pragma unroll
            for (int c = 0; c < 4; c++) S[nt][c] = 0.f;
#pragma unroll
        for (int kk = 0; kk < 64; kk += 8) {
            uint32_t a[4];
            a[0] = Qs[r0 * 68 + kk + tg];
            a[1] = Qs[r1 * 68 + kk + tg];
            a[2] = Qs[r0 * 68 + kk + tg + 4];
            a[3] = Qs[r1 * 68 + kk + tg + 4];
#pragma unroll
            for (int nt = 0; nt < 4; nt++) {
                const int n = wn * 32 + nt * 8 + g;
                uint32_t bf[2];
                bf[0] = Ks[n * 68 + kk + tg];
                bf[1] = Ks[n * 68 + kk + tg + 4];
                mma8(S[nt], a, bf);
            }
        }

        // scale + additive bias
#pragma unroll
        for (int nt = 0; nt < 4; nt++) {
            S[nt][0] *= 0.125f; S[nt][1] *= 0.125f; S[nt][2] *= 0.125f; S[nt][3] *= 0.125f;
        }
        if (phys) {
#pragma unroll
            for (int nt = 0; nt < 4; nt++) {
                const int cb = wn * 32 + nt * 8 + 2 * tg;
                float2 u = *(float2*)&Bb[r0 * 68 + cb];
                float2 v = *(float2*)&Bb[r1 * 68 + cb];
                S[nt][0] += bb * u.x; S[nt][1] += bb * u.y;
                S[nt][2] += bb * v.x; S[nt][3] += bb * v.y;
            }
        }

        // ---- online softmax ----
        float mx0 = -1e30f, mx1 = -1e30f;
#pragma unroll
        for (int nt = 0; nt < 4; nt++) {
            mx0 = fmaxf(mx0, fmaxf(S[nt][0], S[nt][1]));
            mx1 = fmaxf(mx1, fmaxf(S[nt][2], S[nt][3]));
        }
        mx0 = fmaxf(mx0, __shfl_xor_sync(0xffffffffu, mx0, 1));
        mx0 = fmaxf(mx0, __shfl_xor_sync(0xffffffffu, mx0, 2));
        mx1 = fmaxf(mx1, __shfl_xor_sync(0xffffffffu, mx1, 1));
        mx1 = fmaxf(mx1, __shfl_xor_sync(0xffffffffu, mx1, 2));
        if (tg == 0) { rmax[wn * 64 + r0] = mx0; rmax[wn * 64 + r1] = mx1; }
        __syncthreads();
        mx0 = fmaxf(mx0, rmax[(wn ^ 1) * 64 + r0]);
        mx1 = fmaxf(mx1, rmax[(wn ^ 1) * 64 + r1]);
        const float mn0 = fmaxf(m0, mx0), mn1 = fmaxf(m1, mx1);
        const float c0 = __expf(m0 - mn0), c1 = __expf(m1 - mn1);
        float rs0 = 0.f, rs1 = 0.f;
#pragma unroll
        for (int nt = 0; nt < 4; nt++) {
            const float p00 = __expf(S[nt][0] - mn0), p01 = __expf(S[nt][1] - mn0);
            const float p10 = __expf(S[nt][2] - mn1), p11 = __expf(S[nt][3] - mn1);
            rs0 += p00 + p01; rs1 += p10 + p11;
            const int cb = wn * 32 + nt * 8 + 2 * tg;
            *(uint2*)&Ps[r0 * 68 + cb] = make_uint2(f2tf(p00), f2tf(p01));
            *(uint2*)&Ps[r1 * 68 + cb] = make_uint2(f2tf(p10), f2tf(p11));
        }
        rs0 += __shfl_xor_sync(0xffffffffu, rs0, 1);
        rs0 += __shfl_xor_sync(0xffffffffu, rs0, 2);
        rs1 += __shfl_xor_sync(0xffffffffu, rs1, 1);
        rs1 += __shfl_xor_sync(0xffffffffu, rs1, 2);
        if (tg == 0) { rsum[wn * 64 + r0] = rs0; rsum[wn * 64 + r1] = rs1; }
#pragma unroll
        for (int nt = 0; nt < 4; nt++) {
            O[nt][0] *= c0; O[nt][1] *= c0; O[nt][2] *= c1; O[nt][3] *= c1;
        }
        m0 = mn0; m1 = mn1;
        __syncthreads();   // rsum + Ps visible
        rs0 += rsum[(wn ^ 1) * 64 + r0];
        rs1 += rsum[(wn ^ 1) * 64 + r1];
        l0 = l0 * c0 + rs0;
        l1 = l1 * c1 + rs1;

        // ---- O += P V ----
#pragma unroll
        for (int kk = 0; kk < 64; kk += 8) {
            uint32_t a[4];
            a[0] = Ps[r0 * 68 + kk + tg];
            a[1] = Ps[r1 * 68 + kk + tg];
            a[2] = Ps[r0 * 68 + kk + tg + 4];
            a[3] = Ps[r1 * 68 + kk + tg + 4];
#pragma unroll
            for (int nt = 0; nt < 4; nt++) {
                const int n = wn * 32 + nt * 8 + g;
                uint32_t bf[2];
                bf[0] = Vs[(kk + tg) * 68 + n];
                bf[1] = Vs[(kk + tg + 4) * 68 + n];
                mma8(O[nt], a, bf);
            }
        }
    }

    const float i0 = 1.f / l0, i1 = 1.f / l1;
    const size_t obase = (size_t)(b * SEQ + qt * 64) * DMODEL + h * DHEAD;
#pragma unroll
    for (int nt = 0; nt < 4; nt++) {
        const int cc = wn * 32 + nt * 8 + 2 * tg;
        *(uint2*)&att[obase + (size_t)r0 * DMODEL + cc] =
            make_uint2(f2tf(O[nt][0] * i0), f2tf(O[nt][1] * i0));
        *(uint2*)&att[obase + (size_t)r1 * DMODEL + cc] =
            make_uint2(f2tf(O[nt][2] * i1), f2tf(O[nt][3] * i1));
    }
}

// ---------------------------------------------------------------------------
extern "C" void kernel_launch(void* const* d_in, const int* in_sizes, int n_in,
                              void* d_out, int out_size)
{
    const float* x         = (const float*)d_in[0];  // [2,2048,1024]
    const float* attn_bias = (const float*)d_in[1];  // [2,1,2048,2048]
    const float* Wqkv      = (const float*)d_in[2];  // [1024,3072]
    const float* Wproj     = (const float*)d_in[3];  // [1024,1024]
    const float* beta      = (const float*)d_in[4];  // [8]
    float* out = (float*)d_out;                      // [2,2048,1024]

    uint32_t *xc, *wqkvc, *wprojc, *qkvc, *attc;
    cudaGetSymbolAddress((void**)&xc, g_xc);
    cudaGetSymbolAddress((void**)&wqkvc, g_wqkvc);
    cudaGetSymbolAddress((void**)&wprojc, g_wprojc);
    cudaGetSymbolAddress((void**)&qkvc, g_qkv);
    cudaGetSymbolAddress((void**)&attc, g_att);

    cudaFuncSetAttribute(gemm_tc<true>,  cudaFuncAttributeMaxDynamicSharedMemorySize, 70656);
    cudaFuncSetAttribute(gemm_tc<false>, cudaFuncAttributeMaxDynamicSharedMemorySize, 70656);
    cudaFuncSetAttribute(flash_attn_tc,  cudaFuncAttributeMaxDynamicSharedMemorySize, 88064);

    // 0) one-time-per-call tf32 rounding of the fp32 inputs
    {
        int n4;
        n4 = ROWS * DMODEL / 4;
        cvt_tf32_kernel<<<(n4 + 255) / 256, 256>>>((const float4*)x, (uint4*)xc, n4);
        n4 = DMODEL * QKVCOLS / 4;
        cvt_tf32_kernel<<<(n4 + 255) / 256, 256>>>((const float4*)Wqkv, (uint4*)wqkvc, n4);
        n4 = DMODEL * DMODEL / 4;
        cvt_tf32_kernel<<<(n4 + 255) / 256, 256>>>((const float4*)Wproj, (uint4*)wprojc, n4);
    }

    // 1) qkv = x @ Wqkv  (tf32 MMA, emits tf32 bits)
    gemm_tc<true><<<dim3(QKVCOLS / 128, ROWS / 128), 256, 70656>>>(
        xc, wqkvc, qkvc, ROWS, QKVCOLS, DMODEL);

    // 2) flash attention (tf32 MMA), emits tf32 bits head-major
    flash_attn_tc<<<dim3(SEQ / 64, NHEADS, BATCH), 256, 88064>>>(
        qkvc, attn_bias, beta, attc);

    // 3) out = att @ Wproj (tf32 MMA, emits fp32)
    gemm_tc<false><<<dim3(DMODEL / 128, ROWS / 128), 256, 70656>>>(
        attc, wprojc, (uint32_t*)out, ROWS, DMODEL, DMODEL);
}